// round 12
// baseline (speedup 1.0000x reference)
#include <cuda_runtime.h>
#include <cuda_fp16.h>
#include <math.h>
#include <cstdint>

#define BB 32
#define SS 4096
#define EE 512
#define DD 512
#define HH 512
#define MM (BB*SS)
#define NTILES (MM/128)            // 1024 tiles, 32 per batch

// Scratch (static device globals — no runtime allocation)
__device__ float g_dec[BB*HH];
__device__ __half g_Wh[HH*EE];     // fp16 copy of W_enc
__device__ float g_tm[NTILES];     // per-tile local max
__device__ float g_tsum[NTILES];   // per-tile sum of exp
__device__ int   g_tfz[NTILES];    // per-tile first all-zero row (128 = none)
__device__ float g_cpart[NTILES*4*EE];  // per-tile context partials (8MB)
__device__ unsigned g_prep_cnt;    // monotonic grid-barrier ticket counter
__device__ unsigned g_bcnt[BB];    // monotonic per-batch tile-arrival counters

// ---------------------------------------------------------------------------
__device__ __forceinline__ uint32_t smem_u32(const void* p) {
    uint32_t a;
    asm("{ .reg .u64 t; cvta.to.shared.u64 t, %1; cvt.u32.u64 %0, t; }" : "=r"(a) : "l"(p));
    return a;
}
__device__ __forceinline__ void cp_async16(uint32_t dst, const void* src) {
    asm volatile("cp.async.cg.shared.global [%0], [%1], 16;" :: "r"(dst), "l"(src));
}
#define CP_COMMIT() asm volatile("cp.async.commit_group;" ::: "memory")
#define CP_WAIT2()  asm volatile("cp.async.wait_group 2;"  ::: "memory")

#define SW128(o) ((o) ^ (((o) >> 3) & 0x70))

__device__ __forceinline__ void ldsm_x4(uint32_t r[4], uint32_t addr) {
    asm volatile("ldmatrix.sync.aligned.m8n8.x4.shared.b16 {%0,%1,%2,%3}, [%4];"
                 : "=r"(r[0]), "=r"(r[1]), "=r"(r[2]), "=r"(r[3]) : "r"(addr));
}
__device__ __forceinline__ void mma_f16(float c[4], const uint32_t a[4], const uint32_t b[2]) {
    asm volatile(
        "mma.sync.aligned.m16n8k16.row.col.f32.f16.f16.f32 "
        "{%0,%1,%2,%3}, {%4,%5,%6,%7}, {%8,%9}, {%0,%1,%2,%3};\n"
        : "+f"(c[0]), "+f"(c[1]), "+f"(c[2]), "+f"(c[3])
        : "r"(a[0]), "r"(a[1]), "r"(a[2]), "r"(a[3]), "r"(b[0]), "r"(b[1]));
}
__device__ __forceinline__ float tanh_fast(float x) {
    float r;
    asm("tanh.approx.f32 %0, %1;" : "=f"(r) : "f"(x));
    return r;
}

// ---------------------------------------------------------------------------
// THE kernel: persistent, single launch.
//   Prologue: W_enc fp32->fp16 (distributed) + dec GEMV (W row loaded once,
//             looped over batches) + monotonic grid barrier.
//   Tiles:    fp16 HMMA GEMM + bias + tanh + v-dot + online softmax +
//             context partial from resident fp16 A tile.
//   Finish:   last-arriving CTA per batch performs that batch's final reduce.
// ---------------------------------------------------------------------------
#define NTH  512
#define SO_BE   0
#define SO_BD   2048
#define SO_V    4096
#define SO_RED  6144               // 4 x 128 floats (reused as reduce scratch)
#define SO_RMX  8192               // 4 x 128 floats
#define SO_MISC 10240              // ballots/fz/flags + s_w[128]
#define SO_B    11264              // 4 stages x 16384
#define SO_A    76800              // 8 chunks x 16384 = 128KB
#define SMEM_BYTES (SO_A + 131072)

extern __shared__ char dyn_smem[];

__device__ __forceinline__ void load_B(uint32_t sB, int stg, int it, int tid) {
    uint32_t dstb = sB + stg * 16384;
    int hc = it >> 3, kt = it & 7;
    const __half* src = g_Wh + (size_t)(hc * 128) * EE + kt * 64;
    #pragma unroll
    for (int i = 0; i < 2; i++) {
        int c = tid + i * NTH;          // 1024 16B chunks
        int n = c >> 3, kc = c & 7;
        cp_async16(dstb + SW128((uint32_t)(n * 128 + kc * 16)),
                   src + (size_t)n * EE + kc * 8);
    }
}

__device__ __forceinline__ void convert_A(char* smem, const float* __restrict__ enc,
                                          int row0, int c, int tid) {
    #pragma unroll
    for (int i = 0; i < 2; i++) {
        int j = tid + i * NTH;          // 1024 16B units
        int r = j >> 3, u = j & 7;
        const float4* src = (const float4*)(enc + (size_t)(row0 + r) * EE + c * 64 + u * 8);
        float4 f0 = src[0], f1 = src[1];
        __half2 h0 = __floats2half2_rn(f0.x, f0.y);
        __half2 h1 = __floats2half2_rn(f0.z, f0.w);
        __half2 h2 = __floats2half2_rn(f1.x, f1.y);
        __half2 h3 = __floats2half2_rn(f1.z, f1.w);
        uint4 pk;
        pk.x = *(uint32_t*)&h0; pk.y = *(uint32_t*)&h1;
        pk.z = *(uint32_t*)&h2; pk.w = *(uint32_t*)&h3;
        *(uint4*)(smem + SO_A + c * 16384 + SW128((uint32_t)(r * 128 + u * 16))) = pk;
    }
}

__global__ void __launch_bounds__(NTH, 1)
align_all_kernel(const float* __restrict__ enc, const float* __restrict__ dech,
                 const float* __restrict__ W_enc, const float* __restrict__ b_enc,
                 const float* __restrict__ W_dec, const float* __restrict__ b_dec,
                 const float* __restrict__ v, float* __restrict__ out) {
    char* smem = dyn_smem;
    const int tid  = threadIdx.x;
    const int lane = tid & 31;
    const int wid  = tid >> 5;
    const int wm   = wid & 3;
    const int wn   = wid >> 2;
    const int g    = lane >> 2;
    const int t    = lane & 3;

    uint32_t sA = smem_u32(smem + SO_A);
    uint32_t sB = smem_u32(smem + SO_B);
    float* s_be = (float*)(smem + SO_BE);
    float* s_bd = (float*)(smem + SO_BD);
    float* s_v  = (float*)(smem + SO_V);
    float* s_red = (float*)(smem + SO_RED);
    float* s_rmx = (float*)(smem + SO_RMX);
    int*   s_int = (int*)(smem + SO_MISC);
    float* s_w   = (float*)(smem + SO_MISC + 64);

    // ================= PROLOGUE =================
    // (a) W_enc fp32 -> fp16, distributed chip-wide
    for (int i = blockIdx.x * NTH + tid; i < (HH * EE) / 4; i += gridDim.x * NTH) {
        float4 f = ((const float4*)W_enc)[i];
        __half2* o = (__half2*)g_Wh;
        o[i * 2]     = __floats2half2_rn(f.x, f.y);
        o[i * 2 + 1] = __floats2half2_rn(f.z, f.w);
    }
    // (b) dec GEMV: warp owns h, loads W row once, loops all batches
    {
        int gw = blockIdx.x * 16 + wid;
        for (int h = gw; h < HH; h += gridDim.x * 16) {
            const float4* wr = (const float4*)(W_dec + (size_t)h * DD);
            float4 w0 = wr[lane], w1 = wr[lane + 32], w2 = wr[lane + 64], w3 = wr[lane + 96];
            float be = b_dec[h];
            for (int b = 0; b < BB; b++) {
                const float4* xr = (const float4*)(dech + b * DD);
                float4 x0 = xr[lane], x1 = xr[lane + 32], x2 = xr[lane + 64], x3 = xr[lane + 96];
                float s = w0.x*x0.x + w0.y*x0.y + w0.z*x0.z + w0.w*x0.w
                        + w1.x*x1.x + w1.y*x1.y + w1.z*x1.z + w1.w*x1.w
                        + w2.x*x2.x + w2.y*x2.y + w2.z*x2.z + w2.w*x2.w
                        + w3.x*x3.x + w3.y*x3.y + w3.z*x3.z + w3.w*x3.w;
                #pragma unroll
                for (int o = 16; o; o >>= 1) s += __shfl_xor_sync(0xffffffffu, s, o);
                if (lane == 0) g_dec[b * HH + h] = s + be;
            }
        }
    }
    // (c) grid barrier (monotonic ticket; all CTAs co-resident: grid = #SMs, 1 CTA/SM)
    __threadfence();
    __syncthreads();
    if (tid == 0) {
        unsigned tk = atomicAdd(&g_prep_cnt, 1u);
        unsigned tgt = (tk / (unsigned)gridDim.x + 1u) * (unsigned)gridDim.x;
        volatile unsigned* p = &g_prep_cnt;
        while (*p < tgt) { }
    }
    __syncthreads();
    __threadfence();

    const int arow0   = wm * 32 + (lane & 15);
    const int laneHiA = lane >> 4;
    const int nB      = wn * 32 + (lane & 7) + ((lane & 16) >> 1);
    const int laneHiB = (lane >> 3) & 1;

    // ================= PERSISTENT TILE LOOP =================
    bool first = true;
    for (int tile = blockIdx.x; tile < NTILES; tile += gridDim.x) {
        const int row0 = tile * 128;
        const int bb   = row0 / SS;

        if (first) {
            load_B(sB, 0, 0, tid); CP_COMMIT();
            load_B(sB, 1, 1, tid); CP_COMMIT();
            load_B(sB, 2, 2, tid); CP_COMMIT();
            for (int i = tid; i < HH; i += NTH) {
                s_be[i] = b_enc[i];
                s_v[i]  = v[i];
            }
            first = false;
        }
        for (int i = tid; i < HH; i += NTH)
            s_bd[i] = s_be[i] + g_dec[bb * HH + i];

        convert_A(smem, enc, row0, 0, tid);   // chunk 0 blocks; 1-7 overlap below
        __syncthreads();

        float rsum[4] = {0.f, 0.f, 0.f, 0.f};
        float rmax[4] = {0.f, 0.f, 0.f, 0.f};

        for (int hc = 0; hc < 4; hc++) {
            float acc[2][4][4];
            #pragma unroll
            for (int mt = 0; mt < 2; mt++)
                #pragma unroll
                for (int nt = 0; nt < 4; nt++)
                    #pragma unroll
                    for (int c = 0; c < 4; c++) acc[mt][nt][c] = 0.f;

            for (int kt = 0; kt < 8; kt++) {
                const int it = hc * 8 + kt;
                CP_WAIT2();
                __syncthreads();
                if (it + 3 < 32) load_B(sB, (it + 3) & 3, it + 3, tid);
                CP_COMMIT();

                float4 pf[4];
                const bool doA = (hc == 0) && (kt + 1 < 8);
                if (doA) {
                    int c = kt + 1;
                    #pragma unroll
                    for (int i = 0; i < 2; i++) {
                        int j = tid + i * NTH;
                        int r = j >> 3, u = j & 7;
                        const float4* src = (const float4*)(enc + (size_t)(row0 + r) * EE + c * 64 + u * 8);
                        pf[i * 2]     = src[0];
                        pf[i * 2 + 1] = src[1];
                    }
                }

                uint32_t sBs = sB + (it & 3) * 16384;
                uint32_t sAc = sA + kt * 16384;
                #pragma unroll
                for (int kk = 0; kk < 4; kk++) {
                    uint32_t a[2][4];
                    int uA = kk * 2 + laneHiA;
                    #pragma unroll
                    for (int mt = 0; mt < 2; mt++)
                        ldsm_x4(a[mt], sAc + SW128((uint32_t)((arow0 + mt * 16) * 128 + uA * 16)));

                    uint32_t b[4][2];
                    int uB = kk * 2 + laneHiB;
                    #pragma unroll
                    for (int p = 0; p < 2; p++) {
                        uint32_t r[4];
                        int n = nB + p * 16;
                        ldsm_x4(r, sBs + SW128((uint32_t)(n * 128 + uB * 16)));
                        b[2 * p][0] = r[0]; b[2 * p][1] = r[1];
                        b[2 * p + 1][0] = r[2]; b[2 * p + 1][1] = r[3];
                    }
                    #pragma unroll
                    for (int mt = 0; mt < 2; mt++)
                        #pragma unroll
                        for (int nt = 0; nt < 4; nt++)
                            mma_f16(acc[mt][nt], a[mt], b[nt]);
                }

                if (doA) {
                    int c = kt + 1;
                    #pragma unroll
                    for (int i = 0; i < 2; i++) {
                        int j = tid + i * NTH;
                        int r = j >> 3, u = j & 7;
                        __half2 h0 = __floats2half2_rn(pf[i*2].x, pf[i*2].y);
                        __half2 h1 = __floats2half2_rn(pf[i*2].z, pf[i*2].w);
                        __half2 h2 = __floats2half2_rn(pf[i*2+1].x, pf[i*2+1].y);
                        __half2 h3 = __floats2half2_rn(pf[i*2+1].z, pf[i*2+1].w);
                        uint4 pk;
                        pk.x = *(uint32_t*)&h0; pk.y = *(uint32_t*)&h1;
                        pk.z = *(uint32_t*)&h2; pk.w = *(uint32_t*)&h3;
                        *(uint4*)(smem + SO_A + c * 16384 + SW128((uint32_t)(r * 128 + u * 16))) = pk;
                    }
                }
            }

            #pragma unroll
            for (int mt = 0; mt < 2; mt++) {
                #pragma unroll
                for (int nt = 0; nt < 4; nt++) {
                    int h0 = hc * 128 + wn * 32 + nt * 8 + t * 2;
                    #pragma unroll
                    for (int c = 0; c < 4; c++) {
                        int h = h0 + (c & 1);
                        float a  = acc[mt][nt][c];
                        float ev = a + s_be[h];
                        float th = tanh_fast(a + s_bd[h]);
                        int idx = mt * 2 + (c >> 1);
                        rsum[idx] += s_v[h] * th;
                        rmax[idx] = fmaxf(rmax[idx], fabsf(ev));
                    }
                }
            }
        }

        #pragma unroll
        for (int idx = 0; idx < 4; idx++) {
            rsum[idx] += __shfl_xor_sync(0xffffffffu, rsum[idx], 1);
            rsum[idx] += __shfl_xor_sync(0xffffffffu, rsum[idx], 2);
            rmax[idx] = fmaxf(rmax[idx], __shfl_xor_sync(0xffffffffu, rmax[idx], 1));
            rmax[idx] = fmaxf(rmax[idx], __shfl_xor_sync(0xffffffffu, rmax[idx], 2));
        }
        if (t == 0) {
            #pragma unroll
            for (int mt = 0; mt < 2; mt++)
                #pragma unroll
                for (int rh = 0; rh < 2; rh++) {
                    int r = wm * 32 + mt * 16 + rh * 8 + g;
                    s_red[wn * 128 + r] = rsum[mt * 2 + rh];
                    s_rmx[wn * 128 + r] = rmax[mt * 2 + rh];
                }
        }
        __syncthreads();

        // ---- overlap: issue next tile's B preload during the epilogue ----
        {
            const bool more = (tile + gridDim.x) < NTILES;
            if (more) load_B(sB, 0, 0, tid);
            CP_COMMIT();
            if (more) load_B(sB, 1, 1, tid);
            CP_COMMIT();
            if (more) load_B(sB, 2, 2, tid);
            CP_COMMIT();
        }

        // ---- per-tile online softmax ----
        float sc = 0.f, mab = 0.f;
        if (tid < 128) {
            sc  = (s_red[tid] + s_red[128 + tid]) + (s_red[256 + tid] + s_red[384 + tid]);
            mab = fmaxf(fmaxf(s_rmx[tid], s_rmx[128 + tid]),
                        fmaxf(s_rmx[256 + tid], s_rmx[384 + tid]));
            unsigned zb = __ballot_sync(0xffffffffu, mab == 0.f);
            if (lane == 0) s_int[wid] = (int)zb;
        }
        __syncthreads();
        int fz = 128;
        {
            #pragma unroll
            for (int w = 0; w < 4; w++) {
                unsigned m_ = (unsigned)s_int[w];
                if (m_ && fz == 128) fz = w * 32 + __ffs(m_) - 1;
            }
        }
        if (tid < 128) {
            float vmx = (tid < fz) ? sc : -1e30f;
            #pragma unroll
            for (int o = 16; o; o >>= 1) vmx = fmaxf(vmx, __shfl_xor_sync(0xffffffffu, vmx, o));
            if (lane == 0) s_red[wid] = vmx;
        }
        __syncthreads();
        const float mloc = fmaxf(fmaxf(s_red[0], s_red[1]), fmaxf(s_red[2], s_red[3]));
        if (tid < 128) {
            float wgt = (tid < fz) ? exp2f((sc - mloc) * 1.4426950408889634f) : 0.f;
            s_w[tid] = wgt;
            #pragma unroll
            for (int o = 16; o; o >>= 1) wgt += __shfl_xor_sync(0xffffffffu, wgt, o);
            if (lane == 0) s_red[8 + wid] = wgt;
        }
        __syncthreads();
        if (tid == 0) {
            g_tm[tile]   = mloc;
            g_tsum[tile] = (s_red[8] + s_red[9]) + (s_red[10] + s_red[11]);
            g_tfz[tile]  = fz;
        }

        // ---- context partial from the resident fp16 A tile (vectorized) ----
        {
            const int grp = tid >> 7;              // 4 row-groups of 32 rows
            const int idx = tid & 127;             // 4 e-columns per thread
            const int ch  = idx >> 4;              // k-chunk (64 e per chunk)
            const int bo  = (idx & 15) * 8;        // byte offset within 128B row
            const char* aBase = smem + SO_A + ch * 16384;
            float a0 = 0.f, a1 = 0.f, a2 = 0.f, a3 = 0.f;
            #pragma unroll 8
            for (int rr = 0; rr < 32; rr++) {
                int r = grp * 32 + rr;
                float w = s_w[r];
                uint32_t o = (uint32_t)(r * 128 + bo);
                uint2 h2 = *(const uint2*)(aBase + (o ^ ((o >> 3) & 0x70)));
                float2 f0 = __half22float2(*(__half2*)&h2.x);
                float2 f1 = __half22float2(*(__half2*)&h2.y);
                a0 += w * f0.x; a1 += w * f0.y; a2 += w * f1.x; a3 += w * f1.y;
            }
            *(float4*)(g_cpart + ((size_t)tile * 4 + grp) * EE + idx * 4) =
                make_float4(a0, a1, a2, a3);
        }

        // ---- publish tile; last-arriving CTA per batch reduces it ----
        __threadfence();
        __syncthreads();   // also protects A/s_w/s_bd before next tile
        if (tid == 0) {
            unsigned o = atomicAdd(&g_bcnt[bb], 1u);
            s_int[8] = ((o & 31u) == 31u) ? 1 : 0;
        }
        __syncthreads();
        if (s_int[8]) {
            if (wid == 0) {
                int   fzt = g_tfz[bb * 32 + lane];
                float m   = g_tm[bb * 32 + lane];
                float sm  = g_tsum[bb * 32 + lane];
                unsigned zmask = __ballot_sync(0xffffffffu, fzt < 128);
                bool incl = ((zmask & ((1u << lane) - 1u)) == 0u);
                float M = incl ? m : -1e30f;
                #pragma unroll
                for (int o = 16; o; o >>= 1) M = fmaxf(M, __shfl_xor_sync(0xffffffffu, M, o));
                float c = incl ? exp2f((m - M) * 1.4426950408889634f) : 0.f;
                s_red[lane] = c;
                float tw = c * sm;
                #pragma unroll
                for (int o = 16; o; o >>= 1) tw += __shfl_xor_sync(0xffffffffu, tw, o);
                if (lane == 0) s_red[32] = (tw > 0.f) ? 1.f / tw : 0.f;
            }
            __syncthreads();
            float inv = s_red[32];
            float acc = 0.f;
            #pragma unroll 8
            for (int tt = 0; tt < 32; tt++) {
                const float* p = g_cpart + (size_t)(bb * 32 + tt) * (4 * EE);
                acc += s_red[tt] * ((p[tid] + p[512 + tid]) + (p[1024 + tid] + p[1536 + tid]));
            }
            out[bb * EE + tid] = acc * inv;
            __syncthreads();   // s_red free before next tile
        }
    }
}

// ---------------------------------------------------------------------------
extern "C" void kernel_launch(void* const* d_in, const int* in_sizes, int n_in,
                              void* d_out, int out_size) {
    const float* enc    = (const float*)d_in[0];  // [B,S,E]
    const float* dech   = (const float*)d_in[1];  // [B,D]
    const float* W_enc  = (const float*)d_in[2];  // [H,E]
    const float* b_enc  = (const float*)d_in[3];  // [H]
    const float* W_dec  = (const float*)d_in[4];  // [H,D]
    const float* b_dec  = (const float*)d_in[5];  // [H]
    const float* v      = (const float*)d_in[6];  // [H]
    float* out = (float*)d_out;                   // [B,1,E]

    cudaFuncSetAttribute(align_all_kernel,
                         cudaFuncAttributeMaxDynamicSharedMemorySize, SMEM_BYTES);

    int nsm = 148;
    cudaDeviceGetAttribute(&nsm, cudaDevAttrMultiProcessorCount, 0);
    if (nsm < 1 || nsm > NTILES) nsm = 148;

    align_all_kernel<<<nsm, NTH, SMEM_BYTES>>>(enc, dech, W_enc, b_enc,
                                               W_dec, b_dec, v, out);
}

// round 14
// speedup vs baseline: 1.1414x; 1.1414x over previous
#include <cuda_runtime.h>
#include <cuda_fp16.h>
#include <math.h>
#include <cstdint>

#define BB 32
#define SS 4096
#define EE 512
#define DD 512
#define HH 512
#define MM (BB*SS)
#define NTILES (MM/128)            // 1024 tiles, 32 per batch

// Scratch (static device globals — no runtime allocation)
__device__ float g_dec[BB*HH];
__device__ __half g_Wh[HH*EE];     // fp16 copy of W_enc
__device__ float g_tm[NTILES];     // per-tile local max
__device__ float g_tsum[NTILES];   // per-tile sum of exp
__device__ int   g_tfz[NTILES];    // per-tile first all-zero row (128 = none)
__device__ float g_cpart[NTILES*4*EE];  // per-tile context partials (8MB)

// ---------------------------------------------------------------------------
__device__ __forceinline__ uint32_t smem_u32(const void* p) {
    uint32_t a;
    asm("{ .reg .u64 t; cvta.to.shared.u64 t, %1; cvt.u32.u64 %0, t; }" : "=r"(a) : "l"(p));
    return a;
}
__device__ __forceinline__ void cp_async16(uint32_t dst, const void* src) {
    asm volatile("cp.async.cg.shared.global [%0], [%1], 16;" :: "r"(dst), "l"(src));
}
#define CP_COMMIT() asm volatile("cp.async.commit_group;" ::: "memory")
#define CP_WAIT2()  asm volatile("cp.async.wait_group 2;"  ::: "memory")

#define SW128(o) ((o) ^ (((o) >> 3) & 0x70))

__device__ __forceinline__ void ldsm_x4(uint32_t r[4], uint32_t addr) {
    asm volatile("ldmatrix.sync.aligned.m8n8.x4.shared.b16 {%0,%1,%2,%3}, [%4];"
                 : "=r"(r[0]), "=r"(r[1]), "=r"(r[2]), "=r"(r[3]) : "r"(addr));
}
// fp16-accumulate HMMA: D,C are 2x .f16x2 registers
__device__ __forceinline__ void mma_f16acc(uint32_t c[2], const uint32_t a[4], const uint32_t b[2]) {
    asm volatile(
        "mma.sync.aligned.m16n8k16.row.col.f16.f16.f16.f16 "
        "{%0,%1}, {%2,%3,%4,%5}, {%6,%7}, {%0,%1};\n"
        : "+r"(c[0]), "+r"(c[1])
        : "r"(a[0]), "r"(a[1]), "r"(a[2]), "r"(a[3]), "r"(b[0]), "r"(b[1]));
}
__device__ __forceinline__ float tanh_fast(float x) {
    float r;
    asm("tanh.approx.f32 %0, %1;" : "=f"(r) : "f"(x));
    return r;
}

// ---------------------------------------------------------------------------
// Kernel 0: prep — blocks [0,256): W_enc fp32->fp16; blocks [256,512): dec GEMV
// ---------------------------------------------------------------------------
__global__ void prep_kernel(const float* __restrict__ W_enc,
                            const float* __restrict__ dec_hidden,
                            const float* __restrict__ W_dec,
                            const float* __restrict__ b_dec) {
    if (blockIdx.x < 256) {
        int i = blockIdx.x * 256 + threadIdx.x;   // 65536 float4s
        float4 f = ((const float4*)W_enc)[i];
        __half2* o = (__half2*)g_Wh;
        o[i * 2]     = __floats2half2_rn(f.x, f.y);
        o[i * 2 + 1] = __floats2half2_rn(f.z, f.w);
    } else {
        int blk = blockIdx.x - 256;
        int b = blk >> 3;
        int h0 = (blk & 7) * 64;
        __shared__ float4 xs4[128];
        if (threadIdx.x < 128)
            xs4[threadIdx.x] = ((const float4*)dec_hidden)[b * 128 + threadIdx.x];
        __syncthreads();
        int warp = threadIdx.x >> 5, lane = threadIdx.x & 31;
        #pragma unroll
        for (int j = 0; j < 8; j++) {
            int h = h0 + warp * 8 + j;
            const float4* w4 = (const float4*)(W_dec + (size_t)h * DD);
            float sum = 0.f;
            #pragma unroll
            for (int k = 0; k < 4; k++) {
                float4 wv = w4[lane + k * 32];
                float4 x  = xs4[lane + k * 32];
                sum += wv.x * x.x + wv.y * x.y + wv.z * x.z + wv.w * x.w;
            }
            #pragma unroll
            for (int o = 16; o; o >>= 1) sum += __shfl_xor_sync(0xffffffffu, sum, o);
            if (lane == 0) g_dec[b * HH + h] = sum + b_dec[h];
        }
    }
}

// ---------------------------------------------------------------------------
// Kernel 1: PERSISTENT fp16 HMMA (fp16 accumulate) fused GEMM + bias + tanh +
//           v-dot + online softmax + context partial.
// ---------------------------------------------------------------------------
#define NTH  512
#define SO_BE   0
#define SO_BD   2048
#define SO_V    4096
#define SO_RED  6144               // 4 x 128 floats
#define SO_RMX  8192               // 4 x 128 floats
#define SO_MISC 10240              // ballots/fz + s_w[128]
#define SO_B    11264              // 4 stages x 16384
#define SO_A    76800              // 8 chunks x 16384 = 128KB
#define SMEM_BYTES (SO_A + 131072)

extern __shared__ char dyn_smem[];

__device__ __forceinline__ void load_B(uint32_t sB, int stg, int it, int tid) {
    uint32_t dstb = sB + stg * 16384;
    int hc = it >> 3, kt = it & 7;
    const __half* src = g_Wh + (size_t)(hc * 128) * EE + kt * 64;
    #pragma unroll
    for (int i = 0; i < 2; i++) {
        int c = tid + i * NTH;          // 1024 16B chunks
        int n = c >> 3, kc = c & 7;
        cp_async16(dstb + SW128((uint32_t)(n * 128 + kc * 16)),
                   src + (size_t)n * EE + kc * 8);
    }
}

__device__ __forceinline__ void convert_A(char* smem, const float* __restrict__ enc,
                                          int row0, int c, int tid) {
    #pragma unroll
    for (int i = 0; i < 2; i++) {
        int j = tid + i * NTH;          // 1024 16B units
        int r = j >> 3, u = j & 7;
        const float4* src = (const float4*)(enc + (size_t)(row0 + r) * EE + c * 64 + u * 8);
        float4 f0 = src[0], f1 = src[1];
        __half2 h0 = __floats2half2_rn(f0.x, f0.y);
        __half2 h1 = __floats2half2_rn(f0.z, f0.w);
        __half2 h2 = __floats2half2_rn(f1.x, f1.y);
        __half2 h3 = __floats2half2_rn(f1.z, f1.w);
        uint4 pk;
        pk.x = *(uint32_t*)&h0; pk.y = *(uint32_t*)&h1;
        pk.z = *(uint32_t*)&h2; pk.w = *(uint32_t*)&h3;
        *(uint4*)(smem + SO_A + c * 16384 + SW128((uint32_t)(r * 128 + u * 16))) = pk;
    }
}

__global__ void __launch_bounds__(NTH, 1)
align_score_kernel(const float* __restrict__ enc, const float* __restrict__ b_enc,
                   const float* __restrict__ v) {
    char* smem = dyn_smem;
    const int tid  = threadIdx.x;
    const int lane = tid & 31;
    const int wid  = tid >> 5;
    const int wm   = wid & 3;
    const int wn   = wid >> 2;
    const int g    = lane >> 2;
    const int t    = lane & 3;

    uint32_t sA = smem_u32(smem + SO_A);
    uint32_t sB = smem_u32(smem + SO_B);
    float* s_be = (float*)(smem + SO_BE);
    float* s_bd = (float*)(smem + SO_BD);
    float* s_v  = (float*)(smem + SO_V);
    float* s_red = (float*)(smem + SO_RED);
    float* s_rmx = (float*)(smem + SO_RMX);
    int*   s_int = (int*)(smem + SO_MISC);
    float* s_w   = (float*)(smem + SO_MISC + 64);

    const int arow0   = wm * 32 + (lane & 15);
    const int laneHiA = lane >> 4;
    const int nB      = wn * 32 + (lane & 7) + ((lane & 16) >> 1);
    const int laneHiB = (lane >> 3) & 1;

    bool first = true;
    for (int tile = blockIdx.x; tile < NTILES; tile += gridDim.x) {
        const int row0 = tile * 128;
        const int bb   = row0 / SS;

        if (first) {
            load_B(sB, 0, 0, tid); CP_COMMIT();
            load_B(sB, 1, 1, tid); CP_COMMIT();
            load_B(sB, 2, 2, tid); CP_COMMIT();
            for (int i = tid; i < HH; i += NTH) {
                s_be[i] = b_enc[i];
                s_v[i]  = v[i];
            }
            first = false;
        }
        for (int i = tid; i < HH; i += NTH)
            s_bd[i] = s_be[i] + g_dec[bb * HH + i];

        convert_A(smem, enc, row0, 0, tid);   // chunk 0 blocks; 1-7 overlap below
        __syncthreads();

        float rsum[4] = {0.f, 0.f, 0.f, 0.f};
        float rmax[4] = {0.f, 0.f, 0.f, 0.f};

        for (int hc = 0; hc < 4; hc++) {
            uint32_t acc2[2][4][2];   // fp16x2 accumulators
            #pragma unroll
            for (int mt = 0; mt < 2; mt++)
                #pragma unroll
                for (int nt = 0; nt < 4; nt++) {
                    acc2[mt][nt][0] = 0u;
                    acc2[mt][nt][1] = 0u;
                }

            for (int kt = 0; kt < 8; kt++) {
                const int it = hc * 8 + kt;
                CP_WAIT2();
                __syncthreads();
                if (it + 3 < 32) load_B(sB, (it + 3) & 3, it + 3, tid);
                CP_COMMIT();

                // prefetch A chunk kt+1 during hc==0 (LDG now, CVT+STS after MMAs)
                float4 pf[4];
                const bool doA = (hc == 0) && (kt + 1 < 8);
                if (doA) {
                    int c = kt + 1;
                    #pragma unroll
                    for (int i = 0; i < 2; i++) {
                        int j = tid + i * NTH;
                        int r = j >> 3, u = j & 7;
                        const float4* src = (const float4*)(enc + (size_t)(row0 + r) * EE + c * 64 + u * 8);
                        pf[i * 2]     = src[0];
                        pf[i * 2 + 1] = src[1];
                    }
                }

                uint32_t sBs = sB + (it & 3) * 16384;
                uint32_t sAc = sA + kt * 16384;
                #pragma unroll
                for (int kk = 0; kk < 4; kk++) {
                    uint32_t a[2][4];
                    int uA = kk * 2 + laneHiA;
                    #pragma unroll
                    for (int mt = 0; mt < 2; mt++)
                        ldsm_x4(a[mt], sAc + SW128((uint32_t)((arow0 + mt * 16) * 128 + uA * 16)));

                    uint32_t b[4][2];
                    int uB = kk * 2 + laneHiB;
                    #pragma unroll
                    for (int p = 0; p < 2; p++) {
                        uint32_t r[4];
                        int n = nB + p * 16;
                        ldsm_x4(r, sBs + SW128((uint32_t)(n * 128 + uB * 16)));
                        b[2 * p][0] = r[0]; b[2 * p][1] = r[1];
                        b[2 * p + 1][0] = r[2]; b[2 * p + 1][1] = r[3];
                    }
                    #pragma unroll
                    for (int mt = 0; mt < 2; mt++)
                        #pragma unroll
                        for (int nt = 0; nt < 4; nt++)
                            mma_f16acc(acc2[mt][nt], a[mt], b[nt]);
                }

                if (doA) {
                    int c = kt + 1;
                    #pragma unroll
                    for (int i = 0; i < 2; i++) {
                        int j = tid + i * NTH;
                        int r = j >> 3, u = j & 7;
                        __half2 h0 = __floats2half2_rn(pf[i*2].x, pf[i*2].y);
                        __half2 h1 = __floats2half2_rn(pf[i*2].z, pf[i*2].w);
                        __half2 h2 = __floats2half2_rn(pf[i*2+1].x, pf[i*2+1].y);
                        __half2 h3 = __floats2half2_rn(pf[i*2+1].z, pf[i*2+1].w);
                        uint4 pk;
                        pk.x = *(uint32_t*)&h0; pk.y = *(uint32_t*)&h1;
                        pk.z = *(uint32_t*)&h2; pk.w = *(uint32_t*)&h3;
                        *(uint4*)(smem + SO_A + c * 16384 + SW128((uint32_t)(r * 128 + u * 16))) = pk;
                    }
                }
            }

            // epilogue: unpack fp16 accumulators -> fp32, bias + tanh + v-dot + maxabs
            #pragma unroll
            for (int mt = 0; mt < 2; mt++) {
                #pragma unroll
                for (int nt = 0; nt < 4; nt++) {
                    int h0 = hc * 128 + wn * 32 + nt * 8 + t * 2;
                    float2 p0 = __half22float2(*(__half2*)&acc2[mt][nt][0]); // row r
                    float2 p1 = __half22float2(*(__half2*)&acc2[mt][nt][1]); // row r+8
                    {   // (row r, h0) and (row r, h0+1) -> idx mt*2
                        float ev0 = p0.x + s_be[h0];
                        float ev1 = p0.y + s_be[h0 + 1];
                        rsum[mt*2] += s_v[h0] * tanh_fast(p0.x + s_bd[h0])
                                    + s_v[h0 + 1] * tanh_fast(p0.y + s_bd[h0 + 1]);
                        rmax[mt*2] = fmaxf(rmax[mt*2], fmaxf(fabsf(ev0), fabsf(ev1)));
                    }
                    {   // (row r+8, h0) and (row r+8, h0+1) -> idx mt*2+1
                        float ev0 = p1.x + s_be[h0];
                        float ev1 = p1.y + s_be[h0 + 1];
                        rsum[mt*2+1] += s_v[h0] * tanh_fast(p1.x + s_bd[h0])
                                      + s_v[h0 + 1] * tanh_fast(p1.y + s_bd[h0 + 1]);
                        rmax[mt*2+1] = fmaxf(rmax[mt*2+1], fmaxf(fabsf(ev0), fabsf(ev1)));
                    }
                }
            }
        }

        #pragma unroll
        for (int idx = 0; idx < 4; idx++) {
            rsum[idx] += __shfl_xor_sync(0xffffffffu, rsum[idx], 1);
            rsum[idx] += __shfl_xor_sync(0xffffffffu, rsum[idx], 2);
            rmax[idx] = fmaxf(rmax[idx], __shfl_xor_sync(0xffffffffu, rmax[idx], 1));
            rmax[idx] = fmaxf(rmax[idx], __shfl_xor_sync(0xffffffffu, rmax[idx], 2));
        }
        if (t == 0) {
            #pragma unroll
            for (int mt = 0; mt < 2; mt++)
                #pragma unroll
                for (int rh = 0; rh < 2; rh++) {
                    int r = wm * 32 + mt * 16 + rh * 8 + g;
                    s_red[wn * 128 + r] = rsum[mt * 2 + rh];
                    s_rmx[wn * 128 + r] = rmax[mt * 2 + rh];
                }
        }
        __syncthreads();

        // ---- overlap: issue next tile's B preload during the epilogue ----
        {
            const bool more = (tile + gridDim.x) < NTILES;
            if (more) load_B(sB, 0, 0, tid);
            CP_COMMIT();
            if (more) load_B(sB, 1, 1, tid);
            CP_COMMIT();
            if (more) load_B(sB, 2, 2, tid);
            CP_COMMIT();
        }

        // ---- per-tile online softmax ----
        float sc = 0.f, mab = 0.f;
        if (tid < 128) {
            sc  = (s_red[tid] + s_red[128 + tid]) + (s_red[256 + tid] + s_red[384 + tid]);
            mab = fmaxf(fmaxf(s_rmx[tid], s_rmx[128 + tid]),
                        fmaxf(s_rmx[256 + tid], s_rmx[384 + tid]));
            unsigned zb = __ballot_sync(0xffffffffu, mab == 0.f);
            if (lane == 0) s_int[wid] = (int)zb;
        }
        __syncthreads();
        int fz = 128;
        {
            #pragma unroll
            for (int w = 0; w < 4; w++) {
                unsigned m_ = (unsigned)s_int[w];
                if (m_ && fz == 128) fz = w * 32 + __ffs(m_) - 1;
            }
        }
        if (tid < 128) {
            float vmx = (tid < fz) ? sc : -1e30f;
            #pragma unroll
            for (int o = 16; o; o >>= 1) vmx = fmaxf(vmx, __shfl_xor_sync(0xffffffffu, vmx, o));
            if (lane == 0) s_red[wid] = vmx;
        }
        __syncthreads();
        const float mloc = fmaxf(fmaxf(s_red[0], s_red[1]), fmaxf(s_red[2], s_red[3]));
        if (tid < 128) {
            float wgt = (tid < fz) ? exp2f((sc - mloc) * 1.4426950408889634f) : 0.f;
            s_w[tid] = wgt;
            #pragma unroll
            for (int o = 16; o; o >>= 1) wgt += __shfl_xor_sync(0xffffffffu, wgt, o);
            if (lane == 0) s_red[8 + wid] = wgt;
        }
        __syncthreads();
        if (tid == 0) {
            g_tm[tile]   = mloc;
            g_tsum[tile] = (s_red[8] + s_red[9]) + (s_red[10] + s_red[11]);
            g_tfz[tile]  = fz;
        }

        // ---- context partial from the resident fp16 A tile (vectorized) ----
        {
            const int grp = tid >> 7;              // 4 row-groups of 32 rows
            const int idx = tid & 127;             // 4 e-columns per thread
            const int ch  = idx >> 4;              // k-chunk (64 e per chunk)
            const int bo  = (idx & 15) * 8;        // byte offset within 128B row
            const char* aBase = smem + SO_A + ch * 16384;
            float a0 = 0.f, a1 = 0.f, a2 = 0.f, a3 = 0.f;
            #pragma unroll 8
            for (int rr = 0; rr < 32; rr++) {
                int r = grp * 32 + rr;
                float w = s_w[r];
                uint32_t o = (uint32_t)(r * 128 + bo);
                uint2 h2 = *(const uint2*)(aBase + (o ^ ((o >> 3) & 0x70)));
                float2 f0 = __half22float2(*(__half2*)&h2.x);
                float2 f1 = __half22float2(*(__half2*)&h2.y);
                a0 += w * f0.x; a1 += w * f0.y; a2 += w * f1.x; a3 += w * f1.y;
            }
            *(float4*)(g_cpart + ((size_t)tile * 4 + grp) * EE + idx * 4) =
                make_float4(a0, a1, a2, a3);
        }
        __syncthreads();   // A / s_w / s_bd reads complete before next tile overwrites
    }
}

// ---------------------------------------------------------------------------
// Kernel 2: per-batch reduce of tile partials -> out[b][e]
// ---------------------------------------------------------------------------
__global__ void ctx_reduce_kernel(float* __restrict__ out) {
    int b = blockIdx.x;
    int tid = threadIdx.x;   // 512
    __shared__ float s_coef[32];
    __shared__ float s_inv;
    if (tid < 32) {
        int   fzt = g_tfz[b * 32 + tid];
        float m   = g_tm[b * 32 + tid];
        float sm  = g_tsum[b * 32 + tid];
        unsigned zmask = __ballot_sync(0xffffffffu, fzt < 128);
        bool incl = ((zmask & ((1u << tid) - 1u)) == 0u);   // no earlier tile had a zero
        float mv = incl ? m : -1e30f;
        float M = mv;
        #pragma unroll
        for (int o = 16; o; o >>= 1) M = fmaxf(M, __shfl_xor_sync(0xffffffffu, M, o));
        float c = incl ? exp2f((m - M) * 1.4426950408889634f) : 0.f;
        s_coef[tid] = c;
        float tw = c * sm;
        #pragma unroll
        for (int o = 16; o; o >>= 1) tw += __shfl_xor_sync(0xffffffffu, tw, o);
        if (tid == 0) s_inv = (tw > 0.f) ? 1.f / tw : 0.f;
    }
    __syncthreads();
    float inv = s_inv;
    float acc = 0.f;
    #pragma unroll 8
    for (int t = 0; t < 32; t++) {
        const float* p = g_cpart + (size_t)(b * 32 + t) * (4 * EE);
        acc += s_coef[t] * ((p[tid] + p[512 + tid]) + (p[1024 + tid] + p[1536 + tid]));
    }
    out[b * EE + tid] = acc * inv;
}

// ---------------------------------------------------------------------------
extern "C" void kernel_launch(void* const* d_in, const int* in_sizes, int n_in,
                              void* d_out, int out_size) {
    const float* enc    = (const float*)d_in[0];  // [B,S,E]
    const float* dech   = (const float*)d_in[1];  // [B,D]
    const float* W_enc  = (const float*)d_in[2];  // [H,E]
    const float* b_enc  = (const float*)d_in[3];  // [H]
    const float* W_dec  = (const float*)d_in[4];  // [H,D]
    const float* b_dec  = (const float*)d_in[5];  // [H]
    const float* v      = (const float*)d_in[6];  // [H]
    float* out = (float*)d_out;                   // [B,1,E]

    cudaFuncSetAttribute(align_score_kernel,
                         cudaFuncAttributeMaxDynamicSharedMemorySize, SMEM_BYTES);

    int nsm = 148;
    cudaDeviceGetAttribute(&nsm, cudaDevAttrMultiProcessorCount, 0);
    if (nsm < 1 || nsm > NTILES) nsm = 148;

    prep_kernel<<<512, 256>>>(W_enc, dech, W_dec, b_dec);
    align_score_kernel<<<nsm, NTH, SMEM_BYTES>>>(enc, b_enc, v);
    ctx_reduce_kernel<<<BB, EE>>>(out);
}